// round 6
// baseline (speedup 1.0000x reference)
#include <cuda_runtime.h>

// Causal flash attention, fp32, B=4 H=16 S=2048 D=64.
// One CTA = one (batch*head, 64-row q-tile). 256 threads as 16x16,
// each thread owns a 4x4 register tile with row/col stride 16.
// SMEM float4-chunk XOR swizzle for conflict-free LDS.128 in both GEMMs.

constexpr int S_LEN = 2048;
constexpr int D_DIM = 64;
constexpr int BM = 64;
constexpr int BN = 64;

__device__ __forceinline__ float warp16_max(float v) {
    #pragma unroll
    for (int off = 8; off >= 1; off >>= 1)
        v = fmaxf(v, __shfl_xor_sync(0xffffffffu, v, off));
    return v;
}
__device__ __forceinline__ float warp16_sum(float v) {
    #pragma unroll
    for (int off = 8; off >= 1; off >>= 1)
        v += __shfl_xor_sync(0xffffffffu, v, off);
    return v;
}

__global__ __launch_bounds__(256, 2)
void fa_causal_kernel(const float* __restrict__ Q,
                      const float* __restrict__ K,
                      const float* __restrict__ V,
                      float* __restrict__ O)
{
    // Swizzled layouts (float4 granularity): phys4 = row*16 + (chunk ^ (row & 15))
    __shared__ float Qs[BM * D_DIM];   // swizzled [m][k]
    __shared__ float Ks[BN * D_DIM];   // swizzled [n][k]
    __shared__ float Vs[BN * D_DIM];   // plain row-major [n][d]
    __shared__ float Ps[BM * BN];      // swizzled [m][n]

    const int qt = (int)gridDim.x - 1 - (int)blockIdx.x;  // longest CTAs first
    const int bh = blockIdx.y;
    const int q0 = qt * BM;
    const int tid = threadIdx.x;
    const int tx = tid & 15;
    const int ty = tid >> 4;

    const size_t base = (size_t)bh * S_LEN * D_DIM;
    const float* Qg = Q + base;
    const float* Kg = K + base;
    const float* Vg = V + base;
    float*       Og = O + base;

    // ---- load Q tile (scaled by 1/sqrt(D)=0.125), swizzled ----
    {
        const float4* src = (const float4*)(Qg + (size_t)q0 * D_DIM);
        #pragma unroll
        for (int i = 0; i < 4; i++) {
            int f = tid + i * 256;          // float4 index 0..1023
            int m = f >> 4, c = f & 15;
            float4 v = src[f];
            v.x *= 0.125f; v.y *= 0.125f; v.z *= 0.125f; v.w *= 0.125f;
            ((float4*)Qs)[m * 16 + (c ^ (m & 15))] = v;
        }
    }

    float o[4][4];
    float mrow[4], lrow[4];
    #pragma unroll
    for (int i = 0; i < 4; i++) {
        mrow[i] = -1e30f; lrow[i] = 0.f;
        #pragma unroll
        for (int j = 0; j < 4; j++) o[i][j] = 0.f;
    }

    for (int kt = 0; kt <= qt; kt++) {
        const int k0 = kt * BN;
        __syncthreads();   // prev iter done with Ks/Vs/Ps

        // ---- load K (swizzled) and V (plain) tiles ----
        {
            const float4* ksrc = (const float4*)(Kg + (size_t)k0 * D_DIM);
            const float4* vsrc = (const float4*)(Vg + (size_t)k0 * D_DIM);
            #pragma unroll
            for (int i = 0; i < 4; i++) {
                int f = tid + i * 256;
                int n = f >> 4, c = f & 15;
                ((float4*)Ks)[n * 16 + (c ^ (n & 15))] = ksrc[f];
                ((float4*)Vs)[f] = vsrc[f];
            }
        }
        __syncthreads();

        // ---- S = (Q*scale) @ K^T : 4x4 per thread ----
        float s[4][4];
        #pragma unroll
        for (int i = 0; i < 4; i++)
            #pragma unroll
            for (int j = 0; j < 4; j++) s[i][j] = 0.f;

        #pragma unroll 4
        for (int c = 0; c < 16; c++) {
            float4 a[4], b[4];
            #pragma unroll
            for (int i = 0; i < 4; i++)
                a[i] = ((const float4*)Qs)[(ty + 16 * i) * 16 + (c ^ ty)];
            #pragma unroll
            for (int j = 0; j < 4; j++)
                b[j] = ((const float4*)Ks)[(tx + 16 * j) * 16 + (c ^ tx)];
            #pragma unroll
            for (int i = 0; i < 4; i++)
                #pragma unroll
                for (int j = 0; j < 4; j++) {
                    s[i][j] += a[i].x * b[j].x;
                    s[i][j] += a[i].y * b[j].y;
                    s[i][j] += a[i].z * b[j].z;
                    s[i][j] += a[i].w * b[j].w;
                }
        }

        // ---- causal mask (diagonal tile only) ----
        if (kt == qt) {
            #pragma unroll
            for (int i = 0; i < 4; i++)
                #pragma unroll
                for (int j = 0; j < 4; j++)
                    if (tx + 16 * j > ty + 16 * i) s[i][j] = -1e30f;
        }

        // ---- online softmax update ----
        #pragma unroll
        for (int i = 0; i < 4; i++) {
            float mx = fmaxf(fmaxf(s[i][0], s[i][1]), fmaxf(s[i][2], s[i][3]));
            mx = warp16_max(mx);
            float mnew = fmaxf(mrow[i], mx);
            float corr = __expf(mrow[i] - mnew);
            float rsum = 0.f;
            #pragma unroll
            for (int j = 0; j < 4; j++) {
                float p = __expf(s[i][j] - mnew);
                s[i][j] = p;
                rsum += p;
            }
            rsum = warp16_sum(rsum);
            lrow[i] = lrow[i] * corr + rsum;
            mrow[i] = mnew;
            #pragma unroll
            for (int j = 0; j < 4; j++) o[i][j] *= corr;
        }

        // ---- write P to SMEM (swizzled, scalar stores: conflict-free) ----
        #pragma unroll
        for (int i = 0; i < 4; i++) {
            int m = ty + 16 * i;
            #pragma unroll
            for (int j = 0; j < 4; j++) {
                int n = tx + 16 * j;
                int c = n >> 2;
                Ps[m * 64 + (((c ^ ty) << 2) | (n & 3))] = s[i][j];
            }
        }
        __syncthreads();

        // ---- O += P @ V : contraction over n, 4-n chunks ----
        #pragma unroll 4
        for (int c = 0; c < 16; c++) {
            float4 a[4];
            #pragma unroll
            for (int i = 0; i < 4; i++)
                a[i] = ((const float4*)Ps)[(ty + 16 * i) * 16 + (c ^ ty)];

            const int n0 = c * 4;
            float bv[4];
            // n0 + 0
            #pragma unroll
            for (int j = 0; j < 4; j++) bv[j] = Vs[(n0 + 0) * 64 + tx + 16 * j];
            #pragma unroll
            for (int i = 0; i < 4; i++)
                #pragma unroll
                for (int j = 0; j < 4; j++) o[i][j] += a[i].x * bv[j];
            // n0 + 1
            #pragma unroll
            for (int j = 0; j < 4; j++) bv[j] = Vs[(n0 + 1) * 64 + tx + 16 * j];
            #pragma unroll
            for (int i = 0; i < 4; i++)
                #pragma unroll
                for (int j = 0; j < 4; j++) o[i][j] += a[i].y * bv[j];
            // n0 + 2
            #pragma unroll
            for (int j = 0; j < 4; j++) bv[j] = Vs[(n0 + 2) * 64 + tx + 16 * j];
            #pragma unroll
            for (int i = 0; i < 4; i++)
                #pragma unroll
                for (int j = 0; j < 4; j++) o[i][j] += a[i].z * bv[j];
            // n0 + 3
            #pragma unroll
            for (int j = 0; j < 4; j++) bv[j] = Vs[(n0 + 3) * 64 + tx + 16 * j];
            #pragma unroll
            for (int i = 0; i < 4; i++)
                #pragma unroll
                for (int j = 0; j < 4; j++) o[i][j] += a[i].w * bv[j];
        }
    }

    // ---- normalize and store ----
    #pragma unroll
    for (int i = 0; i < 4; i++) {
        float inv = 1.0f / lrow[i];
        int m = q0 + ty + 16 * i;
        #pragma unroll
        for (int j = 0; j < 4; j++)
            Og[(size_t)m * D_DIM + tx + 16 * j] = o[i][j] * inv;
    }
}

extern "C" void kernel_launch(void* const* d_in, const int* in_sizes, int n_in,
                              void* d_out, int out_size) {
    const float* Q = (const float*)d_in[0];
    const float* K = (const float*)d_in[1];
    const float* V = (const float*)d_in[2];
    float* O = (float*)d_out;

    const int bh = in_sizes[0] / (S_LEN * D_DIM);   // B*H = 64
    dim3 grid(S_LEN / BM, bh);
    dim3 block(256);
    fa_causal_kernel<<<grid, block>>>(Q, K, V, O);
}

// round 7
// speedup vs baseline: 1.0014x; 1.0014x over previous
#include <cuda_runtime.h>

// Causal flash attention, fp32, B=4 H=16 S=2048 D=64.
// One CTA = one (batch*head, 64-row q-tile). 256 threads as 16x16,
// each thread owns a 4x4 register tile with row/col stride 16.
// SMEM float4-chunk XOR swizzle for conflict-free LDS.128 in both GEMMs.

constexpr int S_LEN = 2048;
constexpr int D_DIM = 64;
constexpr int BM = 64;
constexpr int BN = 64;

__device__ __forceinline__ float warp16_max(float v) {
    #pragma unroll
    for (int off = 8; off >= 1; off >>= 1)
        v = fmaxf(v, __shfl_xor_sync(0xffffffffu, v, off));
    return v;
}
__device__ __forceinline__ float warp16_sum(float v) {
    #pragma unroll
    for (int off = 8; off >= 1; off >>= 1)
        v += __shfl_xor_sync(0xffffffffu, v, off);
    return v;
}

__global__ __launch_bounds__(256, 2)
void fa_causal_kernel(const float* __restrict__ Q,
                      const float* __restrict__ K,
                      const float* __restrict__ V,
                      float* __restrict__ O)
{
    // Swizzled layouts (float4 granularity): phys4 = row*16 + (chunk ^ (row & 15))
    __shared__ float Qs[BM * D_DIM];   // swizzled [m][k]
    __shared__ float Ks[BN * D_DIM];   // swizzled [n][k]
    __shared__ float Vs[BN * D_DIM];   // plain row-major [n][d]
    __shared__ float Ps[BM * BN];      // swizzled [m][n]

    const int qt = (int)gridDim.x - 1 - (int)blockIdx.x;  // longest CTAs first
    const int bh = blockIdx.y;
    const int q0 = qt * BM;
    const int tid = threadIdx.x;
    const int tx = tid & 15;
    const int ty = tid >> 4;

    const size_t base = (size_t)bh * S_LEN * D_DIM;
    const float* Qg = Q + base;
    const float* Kg = K + base;
    const float* Vg = V + base;
    float*       Og = O + base;

    // ---- load Q tile (scaled by 1/sqrt(D)=0.125), swizzled ----
    {
        const float4* src = (const float4*)(Qg + (size_t)q0 * D_DIM);
        #pragma unroll
        for (int i = 0; i < 4; i++) {
            int f = tid + i * 256;          // float4 index 0..1023
            int m = f >> 4, c = f & 15;
            float4 v = src[f];
            v.x *= 0.125f; v.y *= 0.125f; v.z *= 0.125f; v.w *= 0.125f;
            ((float4*)Qs)[m * 16 + (c ^ (m & 15))] = v;
        }
    }

    float o[4][4];
    float mrow[4], lrow[4];
    #pragma unroll
    for (int i = 0; i < 4; i++) {
        mrow[i] = -1e30f; lrow[i] = 0.f;
        #pragma unroll
        for (int j = 0; j < 4; j++) o[i][j] = 0.f;
    }

    for (int kt = 0; kt <= qt; kt++) {
        const int k0 = kt * BN;
        __syncthreads();   // prev iter done with Ks/Vs/Ps

        // ---- load K (swizzled) and V (plain) tiles ----
        {
            const float4* ksrc = (const float4*)(Kg + (size_t)k0 * D_DIM);
            const float4* vsrc = (const float4*)(Vg + (size_t)k0 * D_DIM);
            #pragma unroll
            for (int i = 0; i < 4; i++) {
                int f = tid + i * 256;
                int n = f >> 4, c = f & 15;
                ((float4*)Ks)[n * 16 + (c ^ (n & 15))] = ksrc[f];
                ((float4*)Vs)[f] = vsrc[f];
            }
        }
        __syncthreads();

        // ---- S = (Q*scale) @ K^T : 4x4 per thread ----
        float s[4][4];
        #pragma unroll
        for (int i = 0; i < 4; i++)
            #pragma unroll
            for (int j = 0; j < 4; j++) s[i][j] = 0.f;

        #pragma unroll 4
        for (int c = 0; c < 16; c++) {
            float4 a[4], b[4];
            #pragma unroll
            for (int i = 0; i < 4; i++)
                a[i] = ((const float4*)Qs)[(ty + 16 * i) * 16 + (c ^ ty)];
            #pragma unroll
            for (int j = 0; j < 4; j++)
                b[j] = ((const float4*)Ks)[(tx + 16 * j) * 16 + (c ^ tx)];
            #pragma unroll
            for (int i = 0; i < 4; i++)
                #pragma unroll
                for (int j = 0; j < 4; j++) {
                    s[i][j] += a[i].x * b[j].x;
                    s[i][j] += a[i].y * b[j].y;
                    s[i][j] += a[i].z * b[j].z;
                    s[i][j] += a[i].w * b[j].w;
                }
        }

        // ---- causal mask (diagonal tile only) ----
        if (kt == qt) {
            #pragma unroll
            for (int i = 0; i < 4; i++)
                #pragma unroll
                for (int j = 0; j < 4; j++)
                    if (tx + 16 * j > ty + 16 * i) s[i][j] = -1e30f;
        }

        // ---- online softmax update ----
        #pragma unroll
        for (int i = 0; i < 4; i++) {
            float mx = fmaxf(fmaxf(s[i][0], s[i][1]), fmaxf(s[i][2], s[i][3]));
            mx = warp16_max(mx);
            float mnew = fmaxf(mrow[i], mx);
            float corr = __expf(mrow[i] - mnew);
            float rsum = 0.f;
            #pragma unroll
            for (int j = 0; j < 4; j++) {
                float p = __expf(s[i][j] - mnew);
                s[i][j] = p;
                rsum += p;
            }
            rsum = warp16_sum(rsum);
            lrow[i] = lrow[i] * corr + rsum;
            mrow[i] = mnew;
            #pragma unroll
            for (int j = 0; j < 4; j++) o[i][j] *= corr;
        }

        // ---- write P to SMEM (swizzled, scalar stores: conflict-free) ----
        #pragma unroll
        for (int i = 0; i < 4; i++) {
            int m = ty + 16 * i;
            #pragma unroll
            for (int j = 0; j < 4; j++) {
                int n = tx + 16 * j;
                int c = n >> 2;
                Ps[m * 64 + (((c ^ ty) << 2) | (n & 3))] = s[i][j];
            }
        }
        __syncthreads();

        // ---- O += P @ V : contraction over n, 4-n chunks ----
        #pragma unroll 4
        for (int c = 0; c < 16; c++) {
            float4 a[4];
            #pragma unroll
            for (int i = 0; i < 4; i++)
                a[i] = ((const float4*)Ps)[(ty + 16 * i) * 16 + (c ^ ty)];

            const int n0 = c * 4;
            float bv[4];
            // n0 + 0
            #pragma unroll
            for (int j = 0; j < 4; j++) bv[j] = Vs[(n0 + 0) * 64 + tx + 16 * j];
            #pragma unroll
            for (int i = 0; i < 4; i++)
                #pragma unroll
                for (int j = 0; j < 4; j++) o[i][j] += a[i].x * bv[j];
            // n0 + 1
            #pragma unroll
            for (int j = 0; j < 4; j++) bv[j] = Vs[(n0 + 1) * 64 + tx + 16 * j];
            #pragma unroll
            for (int i = 0; i < 4; i++)
                #pragma unroll
                for (int j = 0; j < 4; j++) o[i][j] += a[i].y * bv[j];
            // n0 + 2
            #pragma unroll
            for (int j = 0; j < 4; j++) bv[j] = Vs[(n0 + 2) * 64 + tx + 16 * j];
            #pragma unroll
            for (int i = 0; i < 4; i++)
                #pragma unroll
                for (int j = 0; j < 4; j++) o[i][j] += a[i].z * bv[j];
            // n0 + 3
            #pragma unroll
            for (int j = 0; j < 4; j++) bv[j] = Vs[(n0 + 3) * 64 + tx + 16 * j];
            #pragma unroll
            for (int i = 0; i < 4; i++)
                #pragma unroll
                for (int j = 0; j < 4; j++) o[i][j] += a[i].w * bv[j];
        }
    }

    // ---- normalize and store ----
    #pragma unroll
    for (int i = 0; i < 4; i++) {
        float inv = 1.0f / lrow[i];
        int m = q0 + ty + 16 * i;
        #pragma unroll
        for (int j = 0; j < 4; j++)
            Og[(size_t)m * D_DIM + tx + 16 * j] = o[i][j] * inv;
    }
}

extern "C" void kernel_launch(void* const* d_in, const int* in_sizes, int n_in,
                              void* d_out, int out_size) {
    const float* Q = (const float*)d_in[0];
    const float* K = (const float*)d_in[1];
    const float* V = (const float*)d_in[2];
    float* O = (float*)d_out;

    const int bh = in_sizes[0] / (S_LEN * D_DIM);   // B*H = 64
    dim3 grid(S_LEN / BM, bh);
    dim3 block(256);
    fa_causal_kernel<<<grid, block>>>(Q, K, V, O);
}